// round 14
// baseline (speedup 1.0000x reference)
#include <cuda_runtime.h>
#include <cuda_bf16.h>
#include <cstdint>

#define BB 2
#define SS 2048
#define DD 1024
#define HH 16
#define HD 64
#define MM (BB * SS)   // 4096 rows

// Scratch (allocation-free rule: __device__ globals)
__device__ __align__(16) float g_Q[MM * DD];                  // (B,H,S,HD) fp32
__device__ __align__(16) __nv_bfloat16 g_Xh[3 * MM * DD];     // xq,xk,xv hi
__device__ __align__(16) __nv_bfloat16 g_Xl[3 * MM * DD];     // xq,xk,xv lo
__device__ __align__(16) __nv_bfloat16 g_Wh[4 * DD * DD];     // wq,wk,wv,wo hi
__device__ __align__(16) __nv_bfloat16 g_Wl[4 * DD * DD];     // wq,wk,wv,wo lo
__device__ __align__(16) __nv_bfloat16 g_Kh[MM * DD];         // compacted K hi
__device__ __align__(16) __nv_bfloat16 g_Kl[MM * DD];
__device__ __align__(16) __nv_bfloat16 g_Vh[MM * DD];
__device__ __align__(16) __nv_bfloat16 g_Vl[MM * DD];
__device__ __align__(16) __nv_bfloat16 g_Ah[MM * DD];         // attn out hi (B,S,D)
__device__ __align__(16) __nv_bfloat16 g_Al[MM * DD];         // attn out lo
__device__ int g_map[BB * SS];
__device__ int g_cnt[BB];

// ===========================================================================
// helpers
// ===========================================================================
__device__ __forceinline__ uint32_t smem_u32(const void* p) {
    uint32_t a;
    asm("{ .reg .u64 t; cvta.to.shared.u64 t, %1; cvt.u32.u64 %0, t; }"
        : "=r"(a) : "l"(p));
    return a;
}

__device__ __forceinline__ void ldmatrix_x4(uint32_t& r0, uint32_t& r1,
                                            uint32_t& r2, uint32_t& r3,
                                            uint32_t addr) {
    asm volatile("ldmatrix.sync.aligned.m8n8.x4.shared.b16 {%0,%1,%2,%3}, [%4];"
                 : "=r"(r0), "=r"(r1), "=r"(r2), "=r"(r3) : "r"(addr));
}

__device__ __forceinline__ void ldmatrix_x4_trans(uint32_t& r0, uint32_t& r1,
                                                  uint32_t& r2, uint32_t& r3,
                                                  uint32_t addr) {
    asm volatile("ldmatrix.sync.aligned.m8n8.x4.trans.shared.b16 {%0,%1,%2,%3}, [%4];"
                 : "=r"(r0), "=r"(r1), "=r"(r2), "=r"(r3) : "r"(addr));
}

__device__ __forceinline__ void mma_bf16(float* d,
                                         uint32_t a0, uint32_t a1, uint32_t a2, uint32_t a3,
                                         uint32_t b0, uint32_t b1) {
    asm volatile(
        "mma.sync.aligned.m16n8k16.row.col.f32.bf16.bf16.f32 "
        "{%0,%1,%2,%3}, {%4,%5,%6,%7}, {%8,%9}, {%0,%1,%2,%3};"
        : "+f"(d[0]), "+f"(d[1]), "+f"(d[2]), "+f"(d[3])
        : "r"(a0), "r"(a1), "r"(a2), "r"(a3), "r"(b0), "r"(b1));
}

__device__ __forceinline__ uint32_t pack2(float x, float y) {
    __nv_bfloat162 h = __floats2bfloat162_rn(x, y);
    return *reinterpret_cast<uint32_t*>(&h);
}

__device__ __forceinline__ void split4(float x, float y, float z, float w,
                                       uint32_t& h0, uint32_t& h1,
                                       uint32_t& l0, uint32_t& l1) {
    h0 = pack2(x, y); h1 = pack2(z, w);
    float fx = __uint_as_float(h0 << 16), fy = __uint_as_float(h0 & 0xffff0000u);
    float fz = __uint_as_float(h1 << 16), fw = __uint_as_float(h1 & 0xffff0000u);
    l0 = pack2(x - fx, y - fy); l1 = pack2(z - fz, w - fw);
}

#define SW128(o) ((o) ^ (((o) >> 3) & 0x70))

// ===========================================================================
// Conversion kernels: fp32 -> bf16 hi/lo planes
// ===========================================================================
__global__ __launch_bounds__(256) void cvt_x(
    const float* __restrict__ x0, const float* __restrict__ x1,
    const float* __restrict__ x2,
    __nv_bfloat16* __restrict__ H, __nv_bfloat16* __restrict__ L)
{
    const float* src = (blockIdx.z == 0) ? x0 : (blockIdx.z == 1) ? x1 : x2;
    const size_t base = (size_t)blockIdx.z * MM * DD;
    const size_t i = (size_t)blockIdx.x * 256 + threadIdx.x;   // float4 idx
    float4 v = *((const float4*)src + i);
    uint32_t h0, h1, l0, l1;
    split4(v.x, v.y, v.z, v.w, h0, h1, l0, l1);
    *(uint2*)(H + base + i * 4) = make_uint2(h0, h1);
    *(uint2*)(L + base + i * 4) = make_uint2(l0, l1);
}

__global__ __launch_bounds__(256) void cvt_w(
    const float* __restrict__ w0, const float* __restrict__ w1,
    const float* __restrict__ w2, const float* __restrict__ w3,
    __nv_bfloat16* __restrict__ H, __nv_bfloat16* __restrict__ L)
{
    const float* src = (blockIdx.z == 0) ? w0 : (blockIdx.z == 1) ? w1
                       : (blockIdx.z == 2) ? w2 : w3;
    const size_t base = (size_t)blockIdx.z * DD * DD;
    const size_t i = (size_t)blockIdx.x * 256 + threadIdx.x;
    float4 v = *((const float4*)src + i);
    uint32_t h0, h1, l0, l1;
    split4(v.x, v.y, v.z, v.w, h0, h1, l0, l1);
    *(uint2*)(H + base + i * 4) = make_uint2(h0, h1);
    *(uint2*)(L + base + i * 4) = make_uint2(l0, l1);
}

// ===========================================================================
// Pipelined bf16x3 GEMM: CTA tile 128x256, warp tile 64x64, K-chunk 16,
// 4-stage cp.async ring.
// Stage layout (bytes): Ah[0,6144) Al[6144,12288) Bh[12288,24576) Bl[24576,36864)
// Rows are 48B-stride (32B data + 16B pad) for ldmatrix bank spread.
// ===========================================================================
#define STAGE_B 36864
#define PIPE_S 4
#define GEMM_SMEM_P (PIPE_S * STAGE_B)   // 147456

#define GEMM_VARS()                                                            \
    extern __shared__ char smc[];                                              \
    const uint32_t sb = smem_u32(smc);                                         \
    const int tid = threadIdx.x;                                               \
    const int lane = tid & 31;                                                 \
    const int wid = tid >> 5;                                                  \
    const int warp_m = wid & 1;                                                \
    const int warp_n = wid >> 1;                                               \
    const int bm = blockIdx.y * 128;                                           \
    const int bn = blockIdx.x * 256;                                           \
    const uint32_t aoff = (uint32_t)((warp_m * 64 + (lane & 15)) * 48 + (lane >> 4) * 16); \
    const uint32_t boff = (uint32_t)((warp_n * 64 + (lane & 15)) * 48 + (lane >> 4) * 16);

// Per-thread copy plan: 2 A-copies + 4 B-copies of 16B per chunk.
// A idx space: 512 = 2 planes * 128 rows * 2 cols16
// B idx space: 1024 = 2 planes * 256 rows * 2 cols16
#define COPYPLAN_DECL()                                                        \
    const char* srcA[2]; uint32_t dstA[2]; uint32_t szA[2];                    \
    const char* srcB[4]; uint32_t dstB[4];

#define ISSUE_CHUNK(cc, stg)                                                   \
    do {                                                                       \
        uint32_t sb_ = sb + (uint32_t)(stg) * STAGE_B;                         \
        _Pragma("unroll") for (int j_ = 0; j_ < 2; j_++)                       \
            asm volatile("cp.async.cg.shared.global [%0], [%1], 16, %2;"       \
                         :: "r"(sb_ + dstA[j_]), "l"(srcA[j_] + (size_t)(cc) * 32), \
                            "r"(szA[j_]) : "memory");                          \
        _Pragma("unroll") for (int j_ = 0; j_ < 4; j_++)                       \
            asm volatile("cp.async.cg.shared.global [%0], [%1], 16;"           \
                         :: "r"(sb_ + dstB[j_]), "l"(srcB[j_] + (size_t)(cc) * 32) \
                         : "memory");                                          \
        asm volatile("cp.async.commit_group;" ::: "memory");                   \
    } while (0)

#define LDFRAG_COMPUTE(base_)                                                  \
    do {                                                                       \
        uint32_t bh[8][2], bl[8][2];                                           \
        _Pragma("unroll") for (int p = 0; p < 4; p++) {                        \
            uint32_t t0, t1, t2, t3;                                           \
            ldmatrix_x4(t0, t1, t2, t3, (base_) + 12288u + boff + p * 768u);   \
            bh[p * 2][0] = t0;     bh[p * 2][1] = t2;                          \
            bh[p * 2 + 1][0] = t1; bh[p * 2 + 1][1] = t3;                      \
            ldmatrix_x4(t0, t1, t2, t3, (base_) + 24576u + boff + p * 768u);   \
            bl[p * 2][0] = t0;     bl[p * 2][1] = t2;                          \
            bl[p * 2 + 1][0] = t1; bl[p * 2 + 1][1] = t3;                      \
        }                                                                      \
        _Pragma("unroll") for (int mi = 0; mi < 4; mi++) {                     \
            uint32_t a0, a1, a2, a3, c0, c1, c2, c3;                           \
            ldmatrix_x4(a0, a1, a2, a3, (base_) + aoff + mi * 768u);           \
            ldmatrix_x4(c0, c1, c2, c3, (base_) + 6144u + aoff + mi * 768u);   \
            _Pragma("unroll") for (int ni = 0; ni < 8; ni++) {                 \
                float* d = acc[mi][ni];                                        \
                mma_bf16(d, a0, a1, a2, a3, bh[ni][0], bh[ni][1]);             \
                mma_bf16(d, a0, a1, a2, a3, bl[ni][0], bl[ni][1]);             \
                mma_bf16(d, c0, c1, c2, c3, bh[ni][0], bh[ni][1]);             \
            }                                                                  \
        }                                                                      \
    } while (0)

#define PIPE_MAINLOOP()                                                        \
    ISSUE_CHUNK(0, 0); ISSUE_CHUNK(1, 1); ISSUE_CHUNK(2, 2);                   \
    for (int c = 0; c < 64; c++) {                                             \
        if (c < 62)       asm volatile("cp.async.wait_group 2;" ::: "memory"); \
        else if (c == 62) asm volatile("cp.async.wait_group 1;" ::: "memory"); \
        else              asm volatile("cp.async.wait_group 0;" ::: "memory"); \
        __syncthreads();                                                       \
        if (c + 3 < 64) ISSUE_CHUNK(c + 3, (c + 3) & 3);                       \
        LDFRAG_COMPUTE(sb + (uint32_t)(c & 3) * STAGE_B);                      \
    }

// ===========================================================================
// Merged QKV projection GEMM (bf16-plane inputs).
// z: 0 -> Q (fp32 head-split out), 1 -> K, 2 -> V (compacted bf16 planes).
// ===========================================================================
__global__ __launch_bounds__(256) void tc_gemm_qkv(
    const __nv_bfloat16* __restrict__ Xh, const __nv_bfloat16* __restrict__ Xl,
    const __nv_bfloat16* __restrict__ Wh, const __nv_bfloat16* __restrict__ Wl,
    const float* __restrict__ bq, const float* __restrict__ bk,
    const float* __restrict__ bv,
    float* __restrict__ Qout,
    __nv_bfloat16* __restrict__ Kh, __nv_bfloat16* __restrict__ Kl,
    __nv_bfloat16* __restrict__ Vh, __nv_bfloat16* __restrict__ Vl,
    const int* __restrict__ rowmap, const int* __restrict__ cnt)
{
    const int z = blockIdx.z;
    GEMM_VARS();

    const int batch = bm >> 11;
    int nlive = SS;
    if (z > 0) {
        nlive = cnt[batch];
        if ((bm & (SS - 1)) >= ((nlive + 127) & ~127)) return;   // dead tile
    }

    const __nv_bfloat16* Xph = Xh + (size_t)z * MM * DD;
    const __nv_bfloat16* Xpl = Xl + (size_t)z * MM * DD;
    const __nv_bfloat16* Wph = Wh + (size_t)z * DD * DD;
    const __nv_bfloat16* Wpl = Wl + (size_t)z * DD * DD;
    const float* bias = (z == 0) ? bq : (z == 1) ? bk : bv;

    COPYPLAN_DECL();
#pragma unroll
    for (int j = 0; j < 2; j++) {
        int i_ = tid + j * 256;            // 0..511
        int plA_ = i_ >> 8;                // 0..1
        int ii_ = i_ & 255;
        int row_ = ii_ >> 1;               // 0..127
        int col_ = ii_ & 1;                // 0..1
        int live = 1, grow;
        if (z == 0) {
            grow = bm + row_;
        } else {
            int g = rowmap[bm + row_];
            live = (g >= 0);
            grow = live ? g : 0;
        }
        dstA[j] = (uint32_t)(plA_ * 6144 + row_ * 48 + col_ * 16);
        srcA[j] = (const char*)((plA_ ? Xpl : Xph) + (size_t)grow * DD) + col_ * 16;
        szA[j] = live ? 16u : 0u;
    }
#pragma unroll
    for (int j = 0; j < 4; j++) {
        int i_ = tid + j * 256;            // 0..1023
        int plB_ = i_ >> 9;                // 0..1
        int ii_ = i_ & 511;
        int row_ = ii_ >> 1;               // 0..255
        int col_ = ii_ & 1;
        dstB[j] = (uint32_t)(12288 + plB_ * 12288 + row_ * 48 + col_ * 16);
        srcB[j] = (const char*)((plB_ ? Wpl : Wph) + (size_t)(bn + row_) * DD) + col_ * 16;
    }

    float acc[4][8][4];
#pragma unroll
    for (int i = 0; i < 4; i++)
#pragma unroll
        for (int j = 0; j < 8; j++)
#pragma unroll
            for (int k = 0; k < 4; k++) acc[i][j][k] = 0.f;

    PIPE_MAINLOOP();

    // ---- epilogue ----
    __nv_bfloat16* Ph = (z == 1) ? Kh : Vh;
    __nv_bfloat16* Pl = (z == 1) ? Kl : Vl;
#pragma unroll
    for (int mi = 0; mi < 4; mi++) {
#pragma unroll
        for (int ni = 0; ni < 8; ni++) {
            int m0 = bm + warp_m * 64 + mi * 16 + (lane >> 2);
            int n = bn + warp_n * 64 + ni * 8 + (lane & 3) * 2;
            float b0v = bias[n], b1v = bias[n + 1];
#pragma unroll
            for (int half = 0; half < 2; half++) {
                int m = m0 + half * 8;
                float v0 = acc[mi][ni][half * 2 + 0];
                float v1 = acc[mi][ni][half * 2 + 1];
                int s = m & (SS - 1);
                int hh = n >> 6;
                int hd = n & (HD - 1);
                if (z == 0) {
                    float2 v = make_float2(v0 + b0v, v1 + b1v);
                    *(float2*)(Qout + (((size_t)(batch * HH + hh)) * SS + s) * HD + hd) = v;
                } else {
                    if (s < nlive) { v0 += b0v; v1 += b1v; }
                    else           { v0 = 0.f;  v1 = 0.f; }
                    uint32_t hi = pack2(v0, v1);
                    float f0 = __uint_as_float(hi << 16);
                    float f1 = __uint_as_float(hi & 0xffff0000u);
                    uint32_t lo = pack2(v0 - f0, v1 - f1);
                    size_t basei = (((size_t)(batch * HH + hh)) * SS + s) * HD + hd;
                    *(uint32_t*)(Ph + basei) = hi;
                    *(uint32_t*)(Pl + basei) = lo;
                }
            }
        }
    }
}

// ===========================================================================
// Output GEMM: A = attn-out planes, W = wo planes, fp32 out.
// ===========================================================================
__global__ __launch_bounds__(256) void tc_gemm_out(
    const __nv_bfloat16* __restrict__ Ah, const __nv_bfloat16* __restrict__ Al,
    const __nv_bfloat16* __restrict__ Wh, const __nv_bfloat16* __restrict__ Wl,
    const float* __restrict__ bias, float* __restrict__ C)
{
    GEMM_VARS();
    const __nv_bfloat16* Wph = Wh + (size_t)3 * DD * DD;
    const __nv_bfloat16* Wpl = Wl + (size_t)3 * DD * DD;

    COPYPLAN_DECL();
#pragma unroll
    for (int j = 0; j < 2; j++) {
        int i_ = tid + j * 256;
        int plA_ = i_ >> 8;
        int ii_ = i_ & 255;
        int row_ = ii_ >> 1;
        int col_ = ii_ & 1;
        dstA[j] = (uint32_t)(plA_ * 6144 + row_ * 48 + col_ * 16);
        srcA[j] = (const char*)((plA_ ? Al : Ah) + (size_t)(bm + row_) * DD) + col_ * 16;
        szA[j] = 16u;
    }
#pragma unroll
    for (int j = 0; j < 4; j++) {
        int i_ = tid + j * 256;
        int plB_ = i_ >> 9;
        int ii_ = i_ & 511;
        int row_ = ii_ >> 1;
        int col_ = ii_ & 1;
        dstB[j] = (uint32_t)(12288 + plB_ * 12288 + row_ * 48 + col_ * 16);
        srcB[j] = (const char*)((plB_ ? Wpl : Wph) + (size_t)(bn + row_) * DD) + col_ * 16;
    }

    float acc[4][8][4];
#pragma unroll
    for (int i = 0; i < 4; i++)
#pragma unroll
        for (int j = 0; j < 8; j++)
#pragma unroll
            for (int k = 0; k < 4; k++) acc[i][j][k] = 0.f;

    PIPE_MAINLOOP();

#pragma unroll
    for (int mi = 0; mi < 4; mi++) {
#pragma unroll
        for (int ni = 0; ni < 8; ni++) {
            int m0 = bm + warp_m * 64 + mi * 16 + (lane >> 2);
            int n = bn + warp_n * 64 + ni * 8 + (lane & 3) * 2;
            float b0v = bias[n], b1v = bias[n + 1];
#pragma unroll
            for (int half = 0; half < 2; half++) {
                int m = m0 + half * 8;
                float2 v;
                v.x = acc[mi][ni][half * 2 + 0] + b0v;
                v.y = acc[mi][ni][half * 2 + 1] + b1v;
                *(float2*)(C + (size_t)m * DD + n) = v;
            }
        }
    }
}

// ===========================================================================
// Mask compaction (unchanged)
// ===========================================================================
__global__ __launch_bounds__(1024) void compact_idx(
    const int* __restrict__ mask, int* __restrict__ rowmap, int* __restrict__ cnt)
{
    const int b = blockIdx.x;
    __shared__ int wsum[32];
    const int t = threadIdx.x;
    const int lane = t & 31;
    const int w = t >> 5;

    const int p0 = 2 * t, p1 = 2 * t + 1;
    const int m0 = mask[b * SS + p0] != 0;
    const int m1 = mask[b * SS + p1] != 0;
    const int local = m0 + m1;

    rowmap[b * SS + p0] = -1;
    rowmap[b * SS + p1] = -1;

    int v = local;
#pragma unroll
    for (int off = 1; off < 32; off <<= 1) {
        int u = __shfl_up_sync(0xffffffffu, v, off);
        if (lane >= off) v += u;
    }
    if (lane == 31) wsum[w] = v;
    __syncthreads();
    if (w == 0) {
        int s = wsum[lane];
#pragma unroll
        for (int off = 1; off < 32; off <<= 1) {
            int u = __shfl_up_sync(0xffffffffu, s, off);
            if (lane >= off) s += u;
        }
        wsum[lane] = s;
    }
    __syncthreads();

    const int base = (w > 0 ? wsum[w - 1] : 0) + (v - local);
    if (m0) rowmap[b * SS + base] = b * SS + p0;
    if (m1) rowmap[b * SS + base + m0] = b * SS + p1;
    if (t == 1023) cnt[b] = wsum[31];
}

// ===========================================================================
// Tensor-core flash attention, 2-stage cp.async K/V pipeline (unchanged).
// ===========================================================================
#define OFF_QH 0
#define OFF_QL 16384
#define OFF_KV 32768
#define ATTN_SMEM (32768 + 2 * 32768)   // 98304

#define ISSUE_KV(ktv, stg)                                                     \
    do {                                                                       \
        _Pragma("unroll") for (int it = 0; it < 8; it++) {                     \
            int i_ = tid + it * 256;                                           \
            int plane_ = i_ >> 9;                                              \
            int idx_ = i_ & 511;                                               \
            int row_ = idx_ >> 3, ch_ = idx_ & 7;                              \
            const __nv_bfloat16* sp_ =                                         \
                (plane_ == 0) ? Kh : (plane_ == 1) ? Kl : (plane_ == 2) ? Vh : Vl; \
            const char* src_ = (const char*)(sp_ + (bh + (ktv) + row_) * HD) + ch_ * 16; \
            uint32_t dst_ = sbase + (uint32_t)(OFF_KV + (stg) * 32768 + plane_ * 8192 \
                            + SW128((uint32_t)(row_ * 128 + ch_ * 16)));       \
            asm volatile("cp.async.cg.shared.global [%0], [%1], 16;"           \
                         :: "r"(dst_), "l"(src_) : "memory");                  \
        }                                                                      \
        asm volatile("cp.async.commit_group;" ::: "memory");                   \
    } while (0)

__global__ __launch_bounds__(256, 1) void attn_tc(
    const float* __restrict__ Qf,
    const __nv_bfloat16* __restrict__ Kh, const __nv_bfloat16* __restrict__ Kl,
    const __nv_bfloat16* __restrict__ Vh, const __nv_bfloat16* __restrict__ Vl,
    const int* __restrict__ cnt,
    __nv_bfloat16* __restrict__ OutH, __nv_bfloat16* __restrict__ OutL)
{
    extern __shared__ char smb[];
    const uint32_t sbase = smem_u32(smb);

    const int tid = threadIdx.x;
    const int lane = tid & 31;
    const int w = tid >> 5;
    const int b = blockIdx.z, h = blockIdx.y;
    const int q0 = blockIdx.x * 128;
    const int nlive = cnt[b];
    const size_t bh = (size_t)(b * HH + h) * SS;

    const float* Qb = Qf + (bh + q0) * HD;
#pragma unroll
    for (int it = 0; it < 8; it++) {
        int i = tid + it * 256;
        int row = i >> 4, c4 = (i & 15) * 4;
        float4 v = *(const float4*)(Qb + (size_t)row * HD + c4);
        uint32_t h0, h1, l0, l1;
        split4(v.x, v.y, v.z, v.w, h0, h1, l0, l1);
        uint32_t sw = SW128((uint32_t)(row * 128 + c4 * 2));
        *(uint2*)(smb + OFF_QH + sw) = make_uint2(h0, h1);
        *(uint2*)(smb + OFF_QL + sw) = make_uint2(l0, l1);
    }
    __syncthreads();

    uint32_t qh[4][4], ql[4][4];
    {
        const int grp = lane >> 3;
        const int arow = w * 16 + (grp & 1) * 8 + (lane & 7);
        const int adb = (grp >> 1) * 16;
#pragma unroll
        for (int kc = 0; kc < 4; kc++) {
            uint32_t sw = SW128((uint32_t)(arow * 128 + kc * 32 + adb));
            ldmatrix_x4(qh[kc][0], qh[kc][1], qh[kc][2], qh[kc][3], sbase + OFF_QH + sw);
            ldmatrix_x4(ql[kc][0], ql[kc][1], ql[kc][2], ql[kc][3], sbase + OFF_QL + sw);
        }
    }

    float Oacc[8][4];
#pragma unroll
    for (int i = 0; i < 8; i++)
#pragma unroll
        for (int j = 0; j < 4; j++) Oacc[i][j] = 0.f;
    float m0r = -1e30f, m1r = -1e30f, l0r = 0.f, l1r = 0.f;

    const int grp = lane >> 3;
    const int k_keyoff = (grp >> 1) * 8 + (lane & 7);
    const int k_dboff = (grp & 1) * 16;
    const int v_keyoff = (grp & 1) * 8 + (lane & 7);
    const int v_hdoff = (grp >> 1) * 16;

    const int ntile = (nlive + 63) >> 6;
    ISSUE_KV(0, 0);

    for (int t = 0; t < ntile; t++) {
        const int kt = t * 64;
        asm volatile("cp.async.wait_group 0;" ::: "memory");
        __syncthreads();
        if (t + 1 < ntile) ISSUE_KV(kt + 64, (t + 1) & 1);
        const uint32_t kvb = (uint32_t)(OFF_KV + (t & 1) * 32768);

        float sc[8][4];
#pragma unroll
        for (int i = 0; i < 8; i++)
#pragma unroll
            for (int j = 0; j < 4; j++) sc[i][j] = 0.f;

#pragma unroll
        for (int kc = 0; kc < 4; kc++) {
#pragma unroll
            for (int np = 0; np < 4; np++) {
                uint32_t swk = kvb + SW128((uint32_t)((np * 16 + k_keyoff) * 128 + kc * 32 + k_dboff));
                uint32_t kh0, kh1, kh2, kh3, kl0, kl1, kl2, kl3;
                ldmatrix_x4(kh0, kh1, kh2, kh3, sbase + swk);
                ldmatrix_x4(kl0, kl1, kl2, kl3, sbase + swk + 8192);
                mma_bf16(sc[2 * np], qh[kc][0], qh[kc][1], qh[kc][2], qh[kc][3], kh0, kh1);
                mma_bf16(sc[2 * np], qh[kc][0], qh[kc][1], qh[kc][2], qh[kc][3], kl0, kl1);
                mma_bf16(sc[2 * np], ql[kc][0], ql[kc][1], ql[kc][2], ql[kc][3], kh0, kh1);
                mma_bf16(sc[2 * np + 1], qh[kc][0], qh[kc][1], qh[kc][2], qh[kc][3], kh2, kh3);
                mma_bf16(sc[2 * np + 1], qh[kc][0], qh[kc][1], qh[kc][2], qh[kc][3], kl2, kl3);
                mma_bf16(sc[2 * np + 1], ql[kc][0], ql[kc][1], ql[kc][2], ql[kc][3], kh2, kh3);
            }
        }

        const bool tail = (kt + 64 > nlive);
        const int colbase = kt + (lane & 3) * 2;
#pragma unroll
        for (int i = 0; i < 8; i++) {
#pragma unroll
            for (int j = 0; j < 4; j++) sc[i][j] *= 0.125f;
        }
        if (tail) {
#pragma unroll
            for (int i = 0; i < 8; i++) {
                int c0 = colbase + i * 8;
                float bia0 = (c0 < nlive) ? 0.f : -1e9f;
                float bia1 = (c0 + 1 < nlive) ? 0.f : -1e9f;
                sc[i][0] += bia0; sc[i][1] += bia1;
                sc[i][2] += bia0; sc[i][3] += bia1;
            }
        }
        {
            float mx = sc[0][0];
#pragma unroll
            for (int i = 0; i < 8; i++) { mx = fmaxf(mx, sc[i][0]); mx = fmaxf(mx, sc[i][1]); }
            mx = fmaxf(mx, __shfl_xor_sync(0xffffffffu, mx, 1));
            mx = fmaxf(mx, __shfl_xor_sync(0xffffffffu, mx, 2));
            float nm = fmaxf(m0r, mx);
            float corr = __expf(m0r - nm);
            float ps = 0.f;
#pragma unroll
            for (int i = 0; i < 8; i++) {
                sc[i][0] = __expf(sc[i][0] - nm); ps += sc[i][0];
                sc[i][1] = __expf(sc[i][1] - nm); ps += sc[i][1];
            }
            ps += __shfl_xor_sync(0xffffffffu, ps, 1);
            ps += __shfl_xor_sync(0xffffffffu, ps, 2);
            l0r = l0r * corr + ps;
            m0r = nm;
#pragma unroll
            for (int i = 0; i < 8; i++) { Oacc[i][0] *= corr; Oacc[i][1] *= corr; }
        }
        {
            float mx = sc[0][2];
#pragma unroll
            for (int i = 0; i < 8; i++) { mx = fmaxf(mx, sc[i][2]); mx = fmaxf(mx, sc[i][3]); }
            mx = fmaxf(mx, __shfl_xor_sync(0xffffffffu, mx, 1));
            mx = fmaxf(mx, __shfl_xor_sync(0xffffffffu, mx, 2));
            float nm = fmaxf(m1r, mx);
            float corr = __expf(m1r - nm);
            float ps = 0.f;
#pragma unroll
            for (int i = 0; i < 8; i++) {
                sc[i][2] = __expf(sc[i][2] - nm); ps += sc[i][2];
                sc[i][3] = __expf(sc[i][3] - nm); ps += sc[i][3];
            }
            ps += __shfl_xor_sync(0xffffffffu, ps, 1);
            ps += __shfl_xor_sync(0xffffffffu, ps, 2);
            l1r = l1r * corr + ps;
            m1r = nm;
#pragma unroll
            for (int i = 0; i < 8; i++) { Oacc[i][2] *= corr; Oacc[i][3] *= corr; }
        }

#pragma unroll
        for (int kc = 0; kc < 4; kc++) {
            uint32_t ah0, ah1, ah2, ah3, al0, al1, al2, al3;
            split4(sc[2 * kc][0], sc[2 * kc][1], sc[2 * kc][2], sc[2 * kc][3],
                   ah0, ah1, al0, al1);
            split4(sc[2 * kc + 1][0], sc[2 * kc + 1][1], sc[2 * kc + 1][2], sc[2 * kc + 1][3],
                   ah2, ah3, al2, al3);
#pragma unroll
            for (int np = 0; np < 4; np++) {
                uint32_t swv = kvb + 16384u + SW128((uint32_t)((kc * 16 + v_keyoff) * 128 + np * 32 + v_hdoff));
                uint32_t vh0, vh1, vh2, vh3, vl0, vl1, vl2, vl3;
                ldmatrix_x4_trans(vh0, vh1, vh2, vh3, sbase + swv);
                ldmatrix_x4_trans(vl0, vl1, vl2, vl3, sbase + swv + 8192);
                mma_bf16(Oacc[2 * np], ah0, ah1, ah2, ah3, vh0, vh1);
                mma_bf16(Oacc[2 * np], ah0, ah1, ah2, ah3, vl0, vl1);
                mma_bf16(Oacc[2 * np], al0, al1, al2, al3, vh0, vh1);
                mma_bf16(Oacc[2 * np + 1], ah0, ah1, ah2, ah3, vh2, vh3);
                mma_bf16(Oacc[2 * np + 1], ah0, ah1, ah2, ah3, vl2, vl3);
                mma_bf16(Oacc[2 * np + 1], al0, al1, al2, al3, vh2, vh3);
            }
        }
    }

    // --- epilogue: write attn-out hi/lo bf16 planes ---
    const float inv0 = 1.0f / l0r;
    const float inv1 = 1.0f / l1r;
    const int rg0 = q0 + w * 16 + (lane >> 2);
    const int rg1 = rg0 + 8;
    const int cb = h * HD + (lane & 3) * 2;
#pragma unroll
    for (int nt = 0; nt < 8; nt++) {
        int col = cb + nt * 8;
        float v0 = Oacc[nt][0] * inv0, v1 = Oacc[nt][1] * inv0;
        uint32_t hi = pack2(v0, v1);
        float f0 = __uint_as_float(hi << 16), f1 = __uint_as_float(hi & 0xffff0000u);
        uint32_t lo = pack2(v0 - f0, v1 - f1);
        size_t ix0 = ((size_t)(b * SS + rg0)) * DD + col;
        *(uint32_t*)(OutH + ix0) = hi;
        *(uint32_t*)(OutL + ix0) = lo;
        v0 = Oacc[nt][2] * inv1; v1 = Oacc[nt][3] * inv1;
        hi = pack2(v0, v1);
        f0 = __uint_as_float(hi << 16); f1 = __uint_as_float(hi & 0xffff0000u);
        lo = pack2(v0 - f0, v1 - f1);
        size_t ix1 = ((size_t)(b * SS + rg1)) * DD + col;
        *(uint32_t*)(OutH + ix1) = hi;
        *(uint32_t*)(OutL + ix1) = lo;
    }
}

// ---------------------------------------------------------------------------
extern "C" void kernel_launch(void* const* d_in, const int* in_sizes, int n_in,
                              void* d_out, int out_size)
{
    const float* xq = (const float*)d_in[0];
    const float* xk = (const float*)d_in[1];
    const float* xv = (const float*)d_in[2];
    const int*   mask = (const int*)d_in[3];
    const float* wq = (const float*)d_in[4];
    const float* bq = (const float*)d_in[5];
    const float* wk = (const float*)d_in[6];
    const float* bk = (const float*)d_in[7];
    const float* wv = (const float*)d_in[8];
    const float* bv = (const float*)d_in[9];
    const float* wo = (const float*)d_in[10];
    const float* bo = (const float*)d_in[11];
    float* out = (float*)d_out;

    float* Qp;
    __nv_bfloat16 *Xhp, *Xlp, *Whp, *Wlp, *Khp, *Klp, *Vhp, *Vlp, *Ahp, *Alp;
    int *mapp, *cntp;
    cudaGetSymbolAddress((void**)&Qp, g_Q);
    cudaGetSymbolAddress((void**)&Xhp, g_Xh);
    cudaGetSymbolAddress((void**)&Xlp, g_Xl);
    cudaGetSymbolAddress((void**)&Whp, g_Wh);
    cudaGetSymbolAddress((void**)&Wlp, g_Wl);
    cudaGetSymbolAddress((void**)&Khp, g_Kh);
    cudaGetSymbolAddress((void**)&Klp, g_Kl);
    cudaGetSymbolAddress((void**)&Vhp, g_Vh);
    cudaGetSymbolAddress((void**)&Vlp, g_Vl);
    cudaGetSymbolAddress((void**)&Ahp, g_Ah);
    cudaGetSymbolAddress((void**)&Alp, g_Al);
    cudaGetSymbolAddress((void**)&mapp, g_map);
    cudaGetSymbolAddress((void**)&cntp, g_cnt);

    cudaFuncSetAttribute(attn_tc,
                         cudaFuncAttributeMaxDynamicSharedMemorySize, ATTN_SMEM);
    cudaFuncSetAttribute(tc_gemm_qkv,
                         cudaFuncAttributeMaxDynamicSharedMemorySize, GEMM_SMEM_P);
    cudaFuncSetAttribute(tc_gemm_out,
                         cudaFuncAttributeMaxDynamicSharedMemorySize, GEMM_SMEM_P);

    compact_idx<<<BB, 1024>>>(mask, mapp, cntp);
    cvt_x<<<dim3(MM * DD / 4 / 256, 1, 3), 256>>>(xq, xk, xv, Xhp, Xlp);
    cvt_w<<<dim3(DD * DD / 4 / 256, 1, 4), 256>>>(wq, wk, wv, wo, Whp, Wlp);

    tc_gemm_qkv<<<dim3(DD / 256, MM / 128, 3), 256, GEMM_SMEM_P>>>(
        Xhp, Xlp, Whp, Wlp, bq, bk, bv,
        Qp, Khp, Klp, Vhp, Vlp, mapp, cntp);

    attn_tc<<<dim3(SS / 128, HH, BB), 256, ATTN_SMEM>>>(
        Qp, Khp, Klp, Vhp, Vlp, cntp, Ahp, Alp);

    tc_gemm_out<<<dim3(DD / 256, MM / 128), 256, GEMM_SMEM_P>>>(
        Ahp, Alp, Whp, Wlp, bo, out);
}

// round 16
// speedup vs baseline: 1.3604x; 1.3604x over previous
#include <cuda_runtime.h>
#include <cuda_fp16.h>
#include <cstdint>

#define BB 2
#define SS 2048
#define DD 1024
#define HH 16
#define HD 64
#define MM (BB * SS)   // 4096 rows

// Scratch (allocation-free rule: __device__ globals)
__device__ __align__(16) float g_Q[MM * DD];            // (B,H,S,HD) fp32
__device__ __align__(16) __half g_Xh[3 * MM * DD];      // xq,xk,xv hi (A side)
__device__ __align__(16) __half g_Xl[3 * MM * DD];      // xq,xk,xv lo
__device__ __align__(16) __half g_Wh[4 * DD * DD];      // wq,wk,wv,wo single (B side)
__device__ __align__(16) __half g_Kh[MM * DD];          // compacted K single
__device__ __align__(16) __half g_Vh[MM * DD];          // compacted V single
__device__ __align__(16) __half g_Ah[MM * DD];          // attn out hi (B,S,D)
__device__ __align__(16) __half g_Al[MM * DD];          // attn out lo
__device__ int g_map[BB * SS];
__device__ int g_cnt[BB];

// ===========================================================================
// helpers
// ===========================================================================
__device__ __forceinline__ uint32_t smem_u32(const void* p) {
    uint32_t a;
    asm("{ .reg .u64 t; cvta.to.shared.u64 t, %1; cvt.u32.u64 %0, t; }"
        : "=r"(a) : "l"(p));
    return a;
}

__device__ __forceinline__ void ldmatrix_x4(uint32_t& r0, uint32_t& r1,
                                            uint32_t& r2, uint32_t& r3,
                                            uint32_t addr) {
    asm volatile("ldmatrix.sync.aligned.m8n8.x4.shared.b16 {%0,%1,%2,%3}, [%4];"
                 : "=r"(r0), "=r"(r1), "=r"(r2), "=r"(r3) : "r"(addr));
}

__device__ __forceinline__ void ldmatrix_x4_trans(uint32_t& r0, uint32_t& r1,
                                                  uint32_t& r2, uint32_t& r3,
                                                  uint32_t addr) {
    asm volatile("ldmatrix.sync.aligned.m8n8.x4.trans.shared.b16 {%0,%1,%2,%3}, [%4];"
                 : "=r"(r0), "=r"(r1), "=r"(r2), "=r"(r3) : "r"(addr));
}

__device__ __forceinline__ void mma_f16(float* d,
                                        uint32_t a0, uint32_t a1, uint32_t a2, uint32_t a3,
                                        uint32_t b0, uint32_t b1) {
    asm volatile(
        "mma.sync.aligned.m16n8k16.row.col.f32.f16.f16.f32 "
        "{%0,%1,%2,%3}, {%4,%5,%6,%7}, {%8,%9}, {%0,%1,%2,%3};"
        : "+f"(d[0]), "+f"(d[1]), "+f"(d[2]), "+f"(d[3])
        : "r"(a0), "r"(a1), "r"(a2), "r"(a3), "r"(b0), "r"(b1));
}

__device__ __forceinline__ uint32_t pack2h(float x, float y) {
    __half2 h = __floats2half2_rn(x, y);
    return *reinterpret_cast<uint32_t*>(&h);
}

// split 4 floats into fp16 hi pair-regs and lo pair-regs (A-side split)
__device__ __forceinline__ void split4h(float x, float y, float z, float w,
                                        uint32_t& h0, uint32_t& h1,
                                        uint32_t& l0, uint32_t& l1) {
    __half2 a = __floats2half2_rn(x, y);
    __half2 b = __floats2half2_rn(z, w);
    float2 fa = __half22float2(a);
    float2 fb = __half22float2(b);
    h0 = *reinterpret_cast<uint32_t*>(&a);
    h1 = *reinterpret_cast<uint32_t*>(&b);
    l0 = pack2h(x - fa.x, y - fa.y);
    l1 = pack2h(z - fb.x, w - fb.y);
}

#define SW128(o) ((o) ^ (((o) >> 3) & 0x70))

// ===========================================================================
// Conversion kernels
// ===========================================================================
__global__ __launch_bounds__(256) void cvt_x(
    const float* __restrict__ x0, const float* __restrict__ x1,
    const float* __restrict__ x2,
    __half* __restrict__ H, __half* __restrict__ L)
{
    const float* src = (blockIdx.z == 0) ? x0 : (blockIdx.z == 1) ? x1 : x2;
    const size_t base = (size_t)blockIdx.z * MM * DD;
    const size_t i = (size_t)blockIdx.x * 256 + threadIdx.x;   // float4 idx
    float4 v = *((const float4*)src + i);
    uint32_t h0, h1, l0, l1;
    split4h(v.x, v.y, v.z, v.w, h0, h1, l0, l1);
    *(uint2*)(H + base + i * 4) = make_uint2(h0, h1);
    *(uint2*)(L + base + i * 4) = make_uint2(l0, l1);
}

__global__ __launch_bounds__(256) void cvt_w(
    const float* __restrict__ w0, const float* __restrict__ w1,
    const float* __restrict__ w2, const float* __restrict__ w3,
    __half* __restrict__ H)
{
    const float* src = (blockIdx.z == 0) ? w0 : (blockIdx.z == 1) ? w1
                       : (blockIdx.z == 2) ? w2 : w3;
    const size_t base = (size_t)blockIdx.z * DD * DD;
    const size_t i = (size_t)blockIdx.x * 256 + threadIdx.x;
    float4 v = *((const float4*)src + i);
    uint32_t h0 = pack2h(v.x, v.y), h1 = pack2h(v.z, v.w);
    *(uint2*)(H + base + i * 4) = make_uint2(h0, h1);
}

// ===========================================================================
// Pipelined fp16x2 GEMM: CTA tile 128x256, warp tile 64x64, K-chunk 16,
// 4-stage cp.async ring. C = (Ah+Al) @ B^T, B single fp16.
// Stage layout (bytes): Ah[0,6144) Al[6144,12288) B[12288,24576)
// Rows 48B stride (32B data + 16B pad).
// ===========================================================================
#define STAGE_B 24576
#define PIPE_S 4
#define GEMM_SMEM_P (PIPE_S * STAGE_B)   // 98304

#define GEMM_VARS()                                                            \
    extern __shared__ char smc[];                                              \
    const uint32_t sb = smem_u32(smc);                                         \
    const int tid = threadIdx.x;                                               \
    const int lane = tid & 31;                                                 \
    const int wid = tid >> 5;                                                  \
    const int warp_m = wid & 1;                                                \
    const int warp_n = wid >> 1;                                               \
    const int bm = blockIdx.y * 128;                                           \
    const int bn = blockIdx.x * 256;                                           \
    const uint32_t aoff = (uint32_t)((warp_m * 64 + (lane & 15)) * 48 + (lane >> 4) * 16); \
    const uint32_t boff = (uint32_t)((warp_n * 64 + (lane & 15)) * 48 + (lane >> 4) * 16);

// Per-thread copy plan: 2 A-copies + 2 B-copies of 16B per chunk.
#define COPYPLAN_DECL()                                                        \
    const char* srcA[2]; uint32_t dstA[2]; uint32_t szA[2];                    \
    const char* srcB[2]; uint32_t dstB[2];

#define ISSUE_CHUNK(cc, stg)                                                   \
    do {                                                                       \
        uint32_t sb_ = sb + (uint32_t)(stg) * STAGE_B;                         \
        _Pragma("unroll") for (int j_ = 0; j_ < 2; j_++)                       \
            asm volatile("cp.async.cg.shared.global [%0], [%1], 16, %2;"       \
                         :: "r"(sb_ + dstA[j_]), "l"(srcA[j_] + (size_t)(cc) * 32), \
                            "r"(szA[j_]) : "memory");                          \
        _Pragma("unroll") for (int j_ = 0; j_ < 2; j_++)                       \
            asm volatile("cp.async.cg.shared.global [%0], [%1], 16;"           \
                         :: "r"(sb_ + dstB[j_]), "l"(srcB[j_] + (size_t)(cc) * 32) \
                         : "memory");                                          \
        asm volatile("cp.async.commit_group;" ::: "memory");                   \
    } while (0)

#define LDFRAG_COMPUTE(base_)                                                  \
    do {                                                                       \
        uint32_t bh[8][2];                                                     \
        _Pragma("unroll") for (int p = 0; p < 4; p++) {                        \
            uint32_t t0, t1, t2, t3;                                           \
            ldmatrix_x4(t0, t1, t2, t3, (base_) + 12288u + boff + p * 768u);   \
            bh[p * 2][0] = t0;     bh[p * 2][1] = t2;                          \
            bh[p * 2 + 1][0] = t1; bh[p * 2 + 1][1] = t3;                      \
        }                                                                      \
        _Pragma("unroll") for (int mi = 0; mi < 4; mi++) {                     \
            uint32_t a0, a1, a2, a3, c0, c1, c2, c3;                           \
            ldmatrix_x4(a0, a1, a2, a3, (base_) + aoff + mi * 768u);           \
            ldmatrix_x4(c0, c1, c2, c3, (base_) + 6144u + aoff + mi * 768u);   \
            _Pragma("unroll") for (int ni = 0; ni < 8; ni++) {                 \
                float* d = acc[mi][ni];                                        \
                mma_f16(d, a0, a1, a2, a3, bh[ni][0], bh[ni][1]);              \
                mma_f16(d, c0, c1, c2, c3, bh[ni][0], bh[ni][1]);              \
            }                                                                  \
        }                                                                      \
    } while (0)

#define PIPE_MAINLOOP()                                                        \
    ISSUE_CHUNK(0, 0); ISSUE_CHUNK(1, 1); ISSUE_CHUNK(2, 2);                   \
    for (int c = 0; c < 64; c++) {                                             \
        if (c < 62)       asm volatile("cp.async.wait_group 2;" ::: "memory"); \
        else if (c == 62) asm volatile("cp.async.wait_group 1;" ::: "memory"); \
        else              asm volatile("cp.async.wait_group 0;" ::: "memory"); \
        __syncthreads();                                                       \
        if (c + 3 < 64) ISSUE_CHUNK(c + 3, (c + 3) & 3);                       \
        LDFRAG_COMPUTE(sb + (uint32_t)(c & 3) * STAGE_B);                      \
    }

// ===========================================================================
// Merged QKV projection GEMM.
// z: 0 -> Q (fp32 head-split out), 1 -> K, 2 -> V (compacted single fp16).
// ===========================================================================
__global__ __launch_bounds__(256) void tc_gemm_qkv(
    const __half* __restrict__ Xh, const __half* __restrict__ Xl,
    const __half* __restrict__ Wh,
    const float* __restrict__ bq, const float* __restrict__ bk,
    const float* __restrict__ bv,
    float* __restrict__ Qout,
    __half* __restrict__ Kh, __half* __restrict__ Vh,
    const int* __restrict__ rowmap, const int* __restrict__ cnt)
{
    const int z = blockIdx.z;
    GEMM_VARS();

    const int batch = bm >> 11;
    int nlive = SS;
    if (z > 0) {
        nlive = cnt[batch];
        if ((bm & (SS - 1)) >= ((nlive + 127) & ~127)) return;   // dead tile
    }

    const __half* Xph = Xh + (size_t)z * MM * DD;
    const __half* Xpl = Xl + (size_t)z * MM * DD;
    const __half* Wph = Wh + (size_t)z * DD * DD;
    const float* bias = (z == 0) ? bq : (z == 1) ? bk : bv;

    COPYPLAN_DECL();
#pragma unroll
    for (int j = 0; j < 2; j++) {
        int i_ = tid + j * 256;            // 0..511
        int plA_ = i_ >> 8;                // 0..1
        int ii_ = i_ & 255;
        int row_ = ii_ >> 1;               // 0..127
        int col_ = ii_ & 1;                // 0..1
        int live = 1, grow;
        if (z == 0) {
            grow = bm + row_;
        } else {
            int g = rowmap[bm + row_];
            live = (g >= 0);
            grow = live ? g : 0;
        }
        dstA[j] = (uint32_t)(plA_ * 6144 + row_ * 48 + col_ * 16);
        srcA[j] = (const char*)((plA_ ? Xpl : Xph) + (size_t)grow * DD) + col_ * 16;
        szA[j] = live ? 16u : 0u;
    }
#pragma unroll
    for (int j = 0; j < 2; j++) {
        int i_ = tid + j * 256;            // 0..511
        int row_ = i_ >> 1;                // 0..255
        int col_ = i_ & 1;
        dstB[j] = (uint32_t)(12288 + row_ * 48 + col_ * 16);
        srcB[j] = (const char*)(Wph + (size_t)(bn + row_) * DD) + col_ * 16;
    }

    float acc[4][8][4];
#pragma unroll
    for (int i = 0; i < 4; i++)
#pragma unroll
        for (int j = 0; j < 8; j++)
#pragma unroll
            for (int k = 0; k < 4; k++) acc[i][j][k] = 0.f;

    PIPE_MAINLOOP();

    // ---- epilogue ----
    __half* Pp = (z == 1) ? Kh : Vh;
#pragma unroll
    for (int mi = 0; mi < 4; mi++) {
#pragma unroll
        for (int ni = 0; ni < 8; ni++) {
            int m0 = bm + warp_m * 64 + mi * 16 + (lane >> 2);
            int n = bn + warp_n * 64 + ni * 8 + (lane & 3) * 2;
            float b0v = bias[n], b1v = bias[n + 1];
#pragma unroll
            for (int half_ = 0; half_ < 2; half_++) {
                int m = m0 + half_ * 8;
                float v0 = acc[mi][ni][half_ * 2 + 0];
                float v1 = acc[mi][ni][half_ * 2 + 1];
                int s = m & (SS - 1);
                int hh = n >> 6;
                int hd = n & (HD - 1);
                if (z == 0) {
                    float2 v = make_float2(v0 + b0v, v1 + b1v);
                    *(float2*)(Qout + (((size_t)(batch * HH + hh)) * SS + s) * HD + hd) = v;
                } else {
                    if (s < nlive) { v0 += b0v; v1 += b1v; }
                    else           { v0 = 0.f;  v1 = 0.f; }
                    size_t basei = (((size_t)(batch * HH + hh)) * SS + s) * HD + hd;
                    *(uint32_t*)(Pp + basei) = pack2h(v0, v1);
                }
            }
        }
    }
}

// ===========================================================================
// Output GEMM: A = attn-out hi/lo fp16 planes, W = wo single fp16, fp32 out.
// ===========================================================================
__global__ __launch_bounds__(256) void tc_gemm_out(
    const __half* __restrict__ Ah, const __half* __restrict__ Al,
    const __half* __restrict__ Wh,
    const float* __restrict__ bias, float* __restrict__ C)
{
    GEMM_VARS();
    const __half* Wph = Wh + (size_t)3 * DD * DD;

    COPYPLAN_DECL();
#pragma unroll
    for (int j = 0; j < 2; j++) {
        int i_ = tid + j * 256;
        int plA_ = i_ >> 8;
        int ii_ = i_ & 255;
        int row_ = ii_ >> 1;
        int col_ = ii_ & 1;
        dstA[j] = (uint32_t)(plA_ * 6144 + row_ * 48 + col_ * 16);
        srcA[j] = (const char*)((plA_ ? Al : Ah) + (size_t)(bm + row_) * DD) + col_ * 16;
        szA[j] = 16u;
    }
#pragma unroll
    for (int j = 0; j < 2; j++) {
        int i_ = tid + j * 256;
        int row_ = i_ >> 1;
        int col_ = i_ & 1;
        dstB[j] = (uint32_t)(12288 + row_ * 48 + col_ * 16);
        srcB[j] = (const char*)(Wph + (size_t)(bn + row_) * DD) + col_ * 16;
    }

    float acc[4][8][4];
#pragma unroll
    for (int i = 0; i < 4; i++)
#pragma unroll
        for (int j = 0; j < 8; j++)
#pragma unroll
            for (int k = 0; k < 4; k++) acc[i][j][k] = 0.f;

    PIPE_MAINLOOP();

#pragma unroll
    for (int mi = 0; mi < 4; mi++) {
#pragma unroll
        for (int ni = 0; ni < 8; ni++) {
            int m0 = bm + warp_m * 64 + mi * 16 + (lane >> 2);
            int n = bn + warp_n * 64 + ni * 8 + (lane & 3) * 2;
            float b0v = bias[n], b1v = bias[n + 1];
#pragma unroll
            for (int half_ = 0; half_ < 2; half_++) {
                int m = m0 + half_ * 8;
                float2 v;
                v.x = acc[mi][ni][half_ * 2 + 0] + b0v;
                v.y = acc[mi][ni][half_ * 2 + 1] + b1v;
                *(float2*)(C + (size_t)m * DD + n) = v;
            }
        }
    }
}

// ===========================================================================
// Mask compaction (unchanged)
// ===========================================================================
__global__ __launch_bounds__(1024) void compact_idx(
    const int* __restrict__ mask, int* __restrict__ rowmap, int* __restrict__ cnt)
{
    const int b = blockIdx.x;
    __shared__ int wsum[32];
    const int t = threadIdx.x;
    const int lane = t & 31;
    const int w = t >> 5;

    const int p0 = 2 * t, p1 = 2 * t + 1;
    const int m0 = mask[b * SS + p0] != 0;
    const int m1 = mask[b * SS + p1] != 0;
    const int local = m0 + m1;

    rowmap[b * SS + p0] = -1;
    rowmap[b * SS + p1] = -1;

    int v = local;
#pragma unroll
    for (int off = 1; off < 32; off <<= 1) {
        int u = __shfl_up_sync(0xffffffffu, v, off);
        if (lane >= off) v += u;
    }
    if (lane == 31) wsum[w] = v;
    __syncthreads();
    if (w == 0) {
        int s = wsum[lane];
#pragma unroll
        for (int off = 1; off < 32; off <<= 1) {
            int u = __shfl_up_sync(0xffffffffu, s, off);
            if (lane >= off) s += u;
        }
        wsum[lane] = s;
    }
    __syncthreads();

    const int base = (w > 0 ? wsum[w - 1] : 0) + (v - local);
    if (m0) rowmap[b * SS + base] = b * SS + p0;
    if (m1) rowmap[b * SS + base + m0] = b * SS + p1;
    if (t == 1023) cnt[b] = wsum[31];
}

// ===========================================================================
// Tensor-core flash attention, fp16 2-term, 2-stage cp.async K/V pipeline.
// smem: Qh 16K | Ql 16K | 2 KV stages x (K 8K | V 8K).
// ===========================================================================
#define OFF_QH 0
#define OFF_QL 16384
#define OFF_KV 32768
#define ATTN_SMEM (32768 + 2 * 16384)   // 65536

#define ISSUE_KV(ktv, stg)                                                     \
    do {                                                                       \
        _Pragma("unroll") for (int it = 0; it < 4; it++) {                     \
            int i_ = tid + it * 256;                                           \
            int plane_ = i_ >> 9;                                              \
            int idx_ = i_ & 511;                                               \
            int row_ = idx_ >> 3, ch_ = idx_ & 7;                              \
            const __half* sp_ = plane_ ? Vh : Kh;                              \
            const char* src_ = (const char*)(sp_ + (bh + (ktv) + row_) * HD) + ch_ * 16; \
            uint32_t dst_ = sbase + (uint32_t)(OFF_KV + (stg) * 16384 + plane_ * 8192 \
                            + SW128((uint32_t)(row_ * 128 + ch_ * 16)));       \
            asm volatile("cp.async.cg.shared.global [%0], [%1], 16;"           \
                         :: "r"(dst_), "l"(src_) : "memory");                  \
        }                                                                      \
        asm volatile("cp.async.commit_group;" ::: "memory");                   \
    } while (0)

__global__ __launch_bounds__(256, 1) void attn_tc(
    const float* __restrict__ Qf,
    const __half* __restrict__ Kh, const __half* __restrict__ Vh,
    const int* __restrict__ cnt,
    __half* __restrict__ OutH, __half* __restrict__ OutL)
{
    extern __shared__ char smb[];
    const uint32_t sbase = smem_u32(smb);

    const int tid = threadIdx.x;
    const int lane = tid & 31;
    const int w = tid >> 5;
    const int b = blockIdx.z, h = blockIdx.y;
    const int q0 = blockIdx.x * 128;
    const int nlive = cnt[b];
    const size_t bh = (size_t)(b * HH + h) * SS;

    const float* Qb = Qf + (bh + q0) * HD;
#pragma unroll
    for (int it = 0; it < 8; it++) {
        int i = tid + it * 256;
        int row = i >> 4, c4 = (i & 15) * 4;
        float4 v = *(const float4*)(Qb + (size_t)row * HD + c4);
        uint32_t h0, h1, l0, l1;
        split4h(v.x, v.y, v.z, v.w, h0, h1, l0, l1);
        uint32_t sw = SW128((uint32_t)(row * 128 + c4 * 2));
        *(uint2*)(smb + OFF_QH + sw) = make_uint2(h0, h1);
        *(uint2*)(smb + OFF_QL + sw) = make_uint2(l0, l1);
    }
    __syncthreads();

    uint32_t qh[4][4], ql[4][4];
    {
        const int grp = lane >> 3;
        const int arow = w * 16 + (grp & 1) * 8 + (lane & 7);
        const int adb = (grp >> 1) * 16;
#pragma unroll
        for (int kc = 0; kc < 4; kc++) {
            uint32_t sw = SW128((uint32_t)(arow * 128 + kc * 32 + adb));
            ldmatrix_x4(qh[kc][0], qh[kc][1], qh[kc][2], qh[kc][3], sbase + OFF_QH + sw);
            ldmatrix_x4(ql[kc][0], ql[kc][1], ql[kc][2], ql[kc][3], sbase + OFF_QL + sw);
        }
    }

    float Oacc[8][4];
#pragma unroll
    for (int i = 0; i < 8; i++)
#pragma unroll
        for (int j = 0; j < 4; j++) Oacc[i][j] = 0.f;
    float m0r = -1e30f, m1r = -1e30f, l0r = 0.f, l1r = 0.f;

    const int grp = lane >> 3;
    const int k_keyoff = (grp >> 1) * 8 + (lane & 7);
    const int k_dboff = (grp & 1) * 16;
    const int v_keyoff = (grp & 1) * 8 + (lane & 7);
    const int v_hdoff = (grp >> 1) * 16;

    const int ntile = (nlive + 63) >> 6;
    ISSUE_KV(0, 0);

    for (int t = 0; t < ntile; t++) {
        const int kt = t * 64;
        asm volatile("cp.async.wait_group 0;" ::: "memory");
        __syncthreads();
        if (t + 1 < ntile) ISSUE_KV(kt + 64, (t + 1) & 1);
        const uint32_t kvb = (uint32_t)(OFF_KV + (t & 1) * 16384);

        float sc[8][4];
#pragma unroll
        for (int i = 0; i < 8; i++)
#pragma unroll
            for (int j = 0; j < 4; j++) sc[i][j] = 0.f;

#pragma unroll
        for (int kc = 0; kc < 4; kc++) {
#pragma unroll
            for (int np = 0; np < 4; np++) {
                uint32_t swk = kvb + SW128((uint32_t)((np * 16 + k_keyoff) * 128 + kc * 32 + k_dboff));
                uint32_t kh0, kh1, kh2, kh3;
                ldmatrix_x4(kh0, kh1, kh2, kh3, sbase + swk);
                mma_f16(sc[2 * np], qh[kc][0], qh[kc][1], qh[kc][2], qh[kc][3], kh0, kh1);
                mma_f16(sc[2 * np], ql[kc][0], ql[kc][1], ql[kc][2], ql[kc][3], kh0, kh1);
                mma_f16(sc[2 * np + 1], qh[kc][0], qh[kc][1], qh[kc][2], qh[kc][3], kh2, kh3);
                mma_f16(sc[2 * np + 1], ql[kc][0], ql[kc][1], ql[kc][2], ql[kc][3], kh2, kh3);
            }
        }

        const bool tail = (kt + 64 > nlive);
        const int colbase = kt + (lane & 3) * 2;
#pragma unroll
        for (int i = 0; i < 8; i++) {
#pragma unroll
            for (int j = 0; j < 4; j++) sc[i][j] *= 0.125f;
        }
        if (tail) {
#pragma unroll
            for (int i = 0; i < 8; i++) {
                int c0 = colbase + i * 8;
                float bia0 = (c0 < nlive) ? 0.f : -1e9f;
                float bia1 = (c0 + 1 < nlive) ? 0.f : -1e9f;
                sc[i][0] += bia0; sc[i][1] += bia1;
                sc[i][2] += bia0; sc[i][3] += bia1;
            }
        }
        {
            float mx = sc[0][0];
#pragma unroll
            for (int i = 0; i < 8; i++) { mx = fmaxf(mx, sc[i][0]); mx = fmaxf(mx, sc[i][1]); }
            mx = fmaxf(mx, __shfl_xor_sync(0xffffffffu, mx, 1));
            mx = fmaxf(mx, __shfl_xor_sync(0xffffffffu, mx, 2));
            float nm = fmaxf(m0r, mx);
            float corr = __expf(m0r - nm);
            float ps = 0.f;
#pragma unroll
            for (int i = 0; i < 8; i++) {
                sc[i][0] = __expf(sc[i][0] - nm); ps += sc[i][0];
                sc[i][1] = __expf(sc[i][1] - nm); ps += sc[i][1];
            }
            ps += __shfl_xor_sync(0xffffffffu, ps, 1);
            ps += __shfl_xor_sync(0xffffffffu, ps, 2);
            l0r = l0r * corr + ps;
            m0r = nm;
#pragma unroll
            for (int i = 0; i < 8; i++) { Oacc[i][0] *= corr; Oacc[i][1] *= corr; }
        }
        {
            float mx = sc[0][2];
#pragma unroll
            for (int i = 0; i < 8; i++) { mx = fmaxf(mx, sc[i][2]); mx = fmaxf(mx, sc[i][3]); }
            mx = fmaxf(mx, __shfl_xor_sync(0xffffffffu, mx, 1));
            mx = fmaxf(mx, __shfl_xor_sync(0xffffffffu, mx, 2));
            float nm = fmaxf(m1r, mx);
            float corr = __expf(m1r - nm);
            float ps = 0.f;
#pragma unroll
            for (int i = 0; i < 8; i++) {
                sc[i][2] = __expf(sc[i][2] - nm); ps += sc[i][2];
                sc[i][3] = __expf(sc[i][3] - nm); ps += sc[i][3];
            }
            ps += __shfl_xor_sync(0xffffffffu, ps, 1);
            ps += __shfl_xor_sync(0xffffffffu, ps, 2);
            l1r = l1r * corr + ps;
            m1r = nm;
#pragma unroll
            for (int i = 0; i < 8; i++) { Oacc[i][2] *= corr; Oacc[i][3] *= corr; }
        }

#pragma unroll
        for (int kc = 0; kc < 4; kc++) {
            uint32_t ah0, ah1, ah2, ah3, al0, al1, al2, al3;
            split4h(sc[2 * kc][0], sc[2 * kc][1], sc[2 * kc][2], sc[2 * kc][3],
                    ah0, ah1, al0, al1);
            split4h(sc[2 * kc + 1][0], sc[2 * kc + 1][1], sc[2 * kc + 1][2], sc[2 * kc + 1][3],
                    ah2, ah3, al2, al3);
#pragma unroll
            for (int np = 0; np < 4; np++) {
                uint32_t swv = kvb + 8192u + SW128((uint32_t)((kc * 16 + v_keyoff) * 128 + np * 32 + v_hdoff));
                uint32_t vh0, vh1, vh2, vh3;
                ldmatrix_x4_trans(vh0, vh1, vh2, vh3, sbase + swv);
                mma_f16(Oacc[2 * np], ah0, ah1, ah2, ah3, vh0, vh1);
                mma_f16(Oacc[2 * np], al0, al1, al2, al3, vh0, vh1);
                mma_f16(Oacc[2 * np + 1], ah0, ah1, ah2, ah3, vh2, vh3);
                mma_f16(Oacc[2 * np + 1], al0, al1, al2, al3, vh2, vh3);
            }
        }
    }

    // --- epilogue: write attn-out hi/lo fp16 planes ---
    const float inv0 = 1.0f / l0r;
    const float inv1 = 1.0f / l1r;
    const int rg0 = q0 + w * 16 + (lane >> 2);
    const int rg1 = rg0 + 8;
    const int cb = h * HD + (lane & 3) * 2;
#pragma unroll
    for (int nt = 0; nt < 8; nt++) {
        int col = cb + nt * 8;
        {
            float v0 = Oacc[nt][0] * inv0, v1 = Oacc[nt][1] * inv0;
            __half2 hh = __floats2half2_rn(v0, v1);
            float2 fh = __half22float2(hh);
            uint32_t lo = pack2h(v0 - fh.x, v1 - fh.y);
            size_t ix0 = ((size_t)(b * SS + rg0)) * DD + col;
            *(uint32_t*)(OutH + ix0) = *reinterpret_cast<uint32_t*>(&hh);
            *(uint32_t*)(OutL + ix0) = lo;
        }
        {
            float v0 = Oacc[nt][2] * inv1, v1 = Oacc[nt][3] * inv1;
            __half2 hh = __floats2half2_rn(v0, v1);
            float2 fh = __half22float2(hh);
            uint32_t lo = pack2h(v0 - fh.x, v1 - fh.y);
            size_t ix1 = ((size_t)(b * SS + rg1)) * DD + col;
            *(uint32_t*)(OutH + ix1) = *reinterpret_cast<uint32_t*>(&hh);
            *(uint32_t*)(OutL + ix1) = lo;
        }
    }
}

// ---------------------------------------------------------------------------
extern "C" void kernel_launch(void* const* d_in, const int* in_sizes, int n_in,
                              void* d_out, int out_size)
{
    const float* xq = (const float*)d_in[0];
    const float* xk = (const float*)d_in[1];
    const float* xv = (const float*)d_in[2];
    const int*   mask = (const int*)d_in[3];
    const float* wq = (const float*)d_in[4];
    const float* bq = (const float*)d_in[5];
    const float* wk = (const float*)d_in[6];
    const float* bk = (const float*)d_in[7];
    const float* wv = (const float*)d_in[8];
    const float* bv = (const float*)d_in[9];
    const float* wo = (const float*)d_in[10];
    const float* bo = (const float*)d_in[11];
    float* out = (float*)d_out;

    float* Qp;
    __half *Xhp, *Xlp, *Whp, *Khp, *Vhp, *Ahp, *Alp;
    int *mapp, *cntp;
    cudaGetSymbolAddress((void**)&Qp, g_Q);
    cudaGetSymbolAddress((void**)&Xhp, g_Xh);
    cudaGetSymbolAddress((void**)&Xlp, g_Xl);
    cudaGetSymbolAddress((void**)&Whp, g_Wh);
    cudaGetSymbolAddress((void**)&Khp, g_Kh);
    cudaGetSymbolAddress((void**)&Vhp, g_Vh);
    cudaGetSymbolAddress((void**)&Ahp, g_Ah);
    cudaGetSymbolAddress((void**)&Alp, g_Al);
    cudaGetSymbolAddress((void**)&mapp, g_map);
    cudaGetSymbolAddress((void**)&cntp, g_cnt);

    cudaFuncSetAttribute(attn_tc,
                         cudaFuncAttributeMaxDynamicSharedMemorySize, ATTN_SMEM);
    cudaFuncSetAttribute(tc_gemm_qkv,
                         cudaFuncAttributeMaxDynamicSharedMemorySize, GEMM_SMEM_P);
    cudaFuncSetAttribute(tc_gemm_out,
                         cudaFuncAttributeMaxDynamicSharedMemorySize, GEMM_SMEM_P);

    compact_idx<<<BB, 1024>>>(mask, mapp, cntp);
    cvt_x<<<dim3(MM * DD / 4 / 256, 1, 3), 256>>>(xq, xk, xv, Xhp, Xlp);
    cvt_w<<<dim3(DD * DD / 4 / 256, 1, 4), 256>>>(wq, wk, wv, wo, Whp);

    tc_gemm_qkv<<<dim3(DD / 256, MM / 128, 3), 256, GEMM_SMEM_P>>>(
        Xhp, Xlp, Whp, bq, bk, bv,
        Qp, Khp, Vhp, mapp, cntp);

    attn_tc<<<dim3(SS / 128, HH, BB), 256, ATTN_SMEM>>>(
        Qp, Khp, Vhp, cntp, Ahp, Alp);

    tc_gemm_out<<<dim3(DD / 256, MM / 128), 256, GEMM_SMEM_P>>>(
        Ahp, Alp, Whp, bo, out);
}

// round 17
// speedup vs baseline: 2.0523x; 1.5086x over previous
#include <cuda_runtime.h>
#include <cuda_fp16.h>
#include <cstdint>

#define BB 2
#define SS 2048
#define DD 1024
#define HH 16
#define HD 64
#define MM (BB * SS)   // 4096 rows

// Scratch (allocation-free rule: __device__ globals)
__device__ __align__(16) float g_Q[MM * DD];            // (B,H,S,HD) fp32
__device__ __align__(16) __half g_Xh[3 * MM * DD];      // xq,xk,xv fp16
__device__ __align__(16) __half g_Wh[4 * DD * DD];      // wq,wk,wv,wo fp16
__device__ __align__(16) __half g_Kh[MM * DD];          // compacted K fp16
__device__ __align__(16) __half g_Vh[MM * DD];          // compacted V fp16
__device__ __align__(16) __half g_Ah[MM * DD];          // attn out fp16 (B,S,D)
__device__ int g_map[BB * SS];
__device__ int g_cnt[BB];

// ===========================================================================
// helpers
// ===========================================================================
__device__ __forceinline__ uint32_t smem_u32(const void* p) {
    uint32_t a;
    asm("{ .reg .u64 t; cvta.to.shared.u64 t, %1; cvt.u32.u64 %0, t; }"
        : "=r"(a) : "l"(p));
    return a;
}

__device__ __forceinline__ void ldmatrix_x4(uint32_t& r0, uint32_t& r1,
                                            uint32_t& r2, uint32_t& r3,
                                            uint32_t addr) {
    asm volatile("ldmatrix.sync.aligned.m8n8.x4.shared.b16 {%0,%1,%2,%3}, [%4];"
                 : "=r"(r0), "=r"(r1), "=r"(r2), "=r"(r3) : "r"(addr));
}

__device__ __forceinline__ void ldmatrix_x4_trans(uint32_t& r0, uint32_t& r1,
                                                  uint32_t& r2, uint32_t& r3,
                                                  uint32_t addr) {
    asm volatile("ldmatrix.sync.aligned.m8n8.x4.trans.shared.b16 {%0,%1,%2,%3}, [%4];"
                 : "=r"(r0), "=r"(r1), "=r"(r2), "=r"(r3) : "r"(addr));
}

__device__ __forceinline__ void mma_f16(float* d,
                                        uint32_t a0, uint32_t a1, uint32_t a2, uint32_t a3,
                                        uint32_t b0, uint32_t b1) {
    asm volatile(
        "mma.sync.aligned.m16n8k16.row.col.f32.f16.f16.f32 "
        "{%0,%1,%2,%3}, {%4,%5,%6,%7}, {%8,%9}, {%0,%1,%2,%3};"
        : "+f"(d[0]), "+f"(d[1]), "+f"(d[2]), "+f"(d[3])
        : "r"(a0), "r"(a1), "r"(a2), "r"(a3), "r"(b0), "r"(b1));
}

__device__ __forceinline__ uint32_t pack2h(float x, float y) {
    __half2 h = __floats2half2_rn(x, y);
    return *reinterpret_cast<uint32_t*>(&h);
}

#define SW128(o) ((o) ^ (((o) >> 3) & 0x70))

// ===========================================================================
// Conversion kernels: fp32 -> fp16
// ===========================================================================
__global__ __launch_bounds__(256) void cvt_x(
    const float* __restrict__ x0, const float* __restrict__ x1,
    const float* __restrict__ x2,
    __half* __restrict__ H)
{
    const float* src = (blockIdx.z == 0) ? x0 : (blockIdx.z == 1) ? x1 : x2;
    const size_t base = (size_t)blockIdx.z * MM * DD;
    const size_t i = (size_t)blockIdx.x * 256 + threadIdx.x;   // float4 idx
    float4 v = *((const float4*)src + i);
    *(uint2*)(H + base + i * 4) = make_uint2(pack2h(v.x, v.y), pack2h(v.z, v.w));
}

__global__ __launch_bounds__(256) void cvt_w(
    const float* __restrict__ w0, const float* __restrict__ w1,
    const float* __restrict__ w2, const float* __restrict__ w3,
    __half* __restrict__ H)
{
    const float* src = (blockIdx.z == 0) ? w0 : (blockIdx.z == 1) ? w1
                       : (blockIdx.z == 2) ? w2 : w3;
    const size_t base = (size_t)blockIdx.z * DD * DD;
    const size_t i = (size_t)blockIdx.x * 256 + threadIdx.x;
    float4 v = *((const float4*)src + i);
    *(uint2*)(H + base + i * 4) = make_uint2(pack2h(v.x, v.y), pack2h(v.z, v.w));
}

// ===========================================================================
// Pipelined fp16 GEMM: CTA tile 128x256, warp tile 64x64, K-chunk 16,
// 4-stage cp.async ring. Single fp16 both sides.
// Stage layout (bytes): A[0,6144) B[6144,18432)
// Rows 48B stride (32B data + 16B pad) for ldmatrix bank spread.
// ===========================================================================
#define STAGE_B 18432
#define PIPE_S 4
#define GEMM_SMEM_P (PIPE_S * STAGE_B)   // 73728

#define GEMM_VARS()                                                            \
    extern __shared__ char smc[];                                              \
    const uint32_t sb = smem_u32(smc);                                         \
    const int tid = threadIdx.x;                                               \
    const int lane = tid & 31;                                                 \
    const int wid = tid >> 5;                                                  \
    const int warp_m = wid & 1;                                                \
    const int warp_n = wid >> 1;                                               \
    const int bm = blockIdx.y * 128;                                           \
    const int bn = blockIdx.x * 256;                                           \
    const uint32_t aoff = (uint32_t)((warp_m * 64 + (lane & 15)) * 48 + (lane >> 4) * 16); \
    const uint32_t boff = (uint32_t)((warp_n * 64 + (lane & 15)) * 48 + (lane >> 4) * 16);

// Per-thread copy plan: 1 A-copy + 2 B-copies of 16B per chunk.
// A idx space: 256 = 128 rows * 2 cols16 ; B: 512 = 256 rows * 2 cols16
#define COPYPLAN_DECL()                                                        \
    const char* srcA; uint32_t dstA; uint32_t szA;                             \
    const char* srcB[2]; uint32_t dstB[2];

#define ISSUE_CHUNK(cc, stg)                                                   \
    do {                                                                       \
        uint32_t sb_ = sb + (uint32_t)(stg) * STAGE_B;                         \
        asm volatile("cp.async.cg.shared.global [%0], [%1], 16, %2;"           \
                     :: "r"(sb_ + dstA), "l"(srcA + (size_t)(cc) * 32),        \
                        "r"(szA) : "memory");                                  \
        _Pragma("unroll") for (int j_ = 0; j_ < 2; j_++)                       \
            asm volatile("cp.async.cg.shared.global [%0], [%1], 16;"           \
                         :: "r"(sb_ + dstB[j_]), "l"(srcB[j_] + (size_t)(cc) * 32) \
                         : "memory");                                          \
        asm volatile("cp.async.commit_group;" ::: "memory");                   \
    } while (0)

#define LDFRAG_COMPUTE(base_)                                                  \
    do {                                                                       \
        uint32_t bh[8][2];                                                     \
        _Pragma("unroll") for (int p = 0; p < 4; p++) {                        \
            uint32_t t0, t1, t2, t3;                                           \
            ldmatrix_x4(t0, t1, t2, t3, (base_) + 6144u + boff + p * 768u);    \
            bh[p * 2][0] = t0;     bh[p * 2][1] = t2;                          \
            bh[p * 2 + 1][0] = t1; bh[p * 2 + 1][1] = t3;                      \
        }                                                                      \
        _Pragma("unroll") for (int mi = 0; mi < 4; mi++) {                     \
            uint32_t a0, a1, a2, a3;                                           \
            ldmatrix_x4(a0, a1, a2, a3, (base_) + aoff + mi * 768u);           \
            _Pragma("unroll") for (int ni = 0; ni < 8; ni++)                   \
                mma_f16(acc[mi][ni], a0, a1, a2, a3, bh[ni][0], bh[ni][1]);    \
        }                                                                      \
    } while (0)

#define PIPE_MAINLOOP()                                                        \
    ISSUE_CHUNK(0, 0); ISSUE_CHUNK(1, 1); ISSUE_CHUNK(2, 2);                   \
    for (int c = 0; c < 64; c++) {                                             \
        if (c < 62)       asm volatile("cp.async.wait_group 2;" ::: "memory"); \
        else if (c == 62) asm volatile("cp.async.wait_group 1;" ::: "memory"); \
        else              asm volatile("cp.async.wait_group 0;" ::: "memory"); \
        __syncthreads();                                                       \
        if (c + 3 < 64) ISSUE_CHUNK(c + 3, (c + 3) & 3);                       \
        LDFRAG_COMPUTE(sb + (uint32_t)(c & 3) * STAGE_B);                      \
    }

// ===========================================================================
// Merged QKV projection GEMM.
// z: 0 -> Q (fp32 head-split out), 1 -> K, 2 -> V (compacted fp16).
// ===========================================================================
__global__ __launch_bounds__(256) void tc_gemm_qkv(
    const __half* __restrict__ Xh, const __half* __restrict__ Wh,
    const float* __restrict__ bq, const float* __restrict__ bk,
    const float* __restrict__ bv,
    float* __restrict__ Qout,
    __half* __restrict__ Kh, __half* __restrict__ Vh,
    const int* __restrict__ rowmap, const int* __restrict__ cnt)
{
    const int z = blockIdx.z;
    GEMM_VARS();

    const int batch = bm >> 11;
    int nlive = SS;
    if (z > 0) {
        nlive = cnt[batch];
        if ((bm & (SS - 1)) >= ((nlive + 127) & ~127)) return;   // dead tile
    }

    const __half* Xph = Xh + (size_t)z * MM * DD;
    const __half* Wph = Wh + (size_t)z * DD * DD;
    const float* bias = (z == 0) ? bq : (z == 1) ? bk : bv;

    COPYPLAN_DECL();
    {
        int row_ = tid >> 1;               // 0..127
        int col_ = tid & 1;                // 0..1
        int live = 1, grow;
        if (z == 0) {
            grow = bm + row_;
        } else {
            int g = rowmap[bm + row_];
            live = (g >= 0);
            grow = live ? g : 0;
        }
        dstA = (uint32_t)(row_ * 48 + col_ * 16);
        srcA = (const char*)(Xph + (size_t)grow * DD) + col_ * 16;
        szA = live ? 16u : 0u;
    }
#pragma unroll
    for (int j = 0; j < 2; j++) {
        int i_ = tid + j * 256;            // 0..511
        int row_ = i_ >> 1;                // 0..255
        int col_ = i_ & 1;
        dstB[j] = (uint32_t)(6144 + row_ * 48 + col_ * 16);
        srcB[j] = (const char*)(Wph + (size_t)(bn + row_) * DD) + col_ * 16;
    }

    float acc[4][8][4];
#pragma unroll
    for (int i = 0; i < 4; i++)
#pragma unroll
        for (int j = 0; j < 8; j++)
#pragma unroll
            for (int k = 0; k < 4; k++) acc[i][j][k] = 0.f;

    PIPE_MAINLOOP();

    // ---- epilogue ----
    __half* Pp = (z == 1) ? Kh : Vh;
#pragma unroll
    for (int mi = 0; mi < 4; mi++) {
#pragma unroll
        for (int ni = 0; ni < 8; ni++) {
            int m0 = bm + warp_m * 64 + mi * 16 + (lane >> 2);
            int n = bn + warp_n * 64 + ni * 8 + (lane & 3) * 2;
            float b0v = bias[n], b1v = bias[n + 1];
#pragma unroll
            for (int half_ = 0; half_ < 2; half_++) {
                int m = m0 + half_ * 8;
                float v0 = acc[mi][ni][half_ * 2 + 0];
                float v1 = acc[mi][ni][half_ * 2 + 1];
                int s = m & (SS - 1);
                int hh = n >> 6;
                int hd = n & (HD - 1);
                if (z == 0) {
                    float2 v = make_float2(v0 + b0v, v1 + b1v);
                    *(float2*)(Qout + (((size_t)(batch * HH + hh)) * SS + s) * HD + hd) = v;
                } else {
                    if (s < nlive) { v0 += b0v; v1 += b1v; }
                    else           { v0 = 0.f;  v1 = 0.f; }
                    size_t basei = (((size_t)(batch * HH + hh)) * SS + s) * HD + hd;
                    *(uint32_t*)(Pp + basei) = pack2h(v0, v1);
                }
            }
        }
    }
}

// ===========================================================================
// Output GEMM: A = attn-out fp16, W = wo fp16, fp32 out.
// ===========================================================================
__global__ __launch_bounds__(256) void tc_gemm_out(
    const __half* __restrict__ Ah, const __half* __restrict__ Wh,
    const float* __restrict__ bias, float* __restrict__ C)
{
    GEMM_VARS();
    const __half* Wph = Wh + (size_t)3 * DD * DD;

    COPYPLAN_DECL();
    {
        int row_ = tid >> 1;
        int col_ = tid & 1;
        dstA = (uint32_t)(row_ * 48 + col_ * 16);
        srcA = (const char*)(Ah + (size_t)(bm + row_) * DD) + col_ * 16;
        szA = 16u;
    }
#pragma unroll
    for (int j = 0; j < 2; j++) {
        int i_ = tid + j * 256;
        int row_ = i_ >> 1;
        int col_ = i_ & 1;
        dstB[j] = (uint32_t)(6144 + row_ * 48 + col_ * 16);
        srcB[j] = (const char*)(Wph + (size_t)(bn + row_) * DD) + col_ * 16;
    }

    float acc[4][8][4];
#pragma unroll
    for (int i = 0; i < 4; i++)
#pragma unroll
        for (int j = 0; j < 8; j++)
#pragma unroll
            for (int k = 0; k < 4; k++) acc[i][j][k] = 0.f;

    PIPE_MAINLOOP();

#pragma unroll
    for (int mi = 0; mi < 4; mi++) {
#pragma unroll
        for (int ni = 0; ni < 8; ni++) {
            int m0 = bm + warp_m * 64 + mi * 16 + (lane >> 2);
            int n = bn + warp_n * 64 + ni * 8 + (lane & 3) * 2;
            float b0v = bias[n], b1v = bias[n + 1];
#pragma unroll
            for (int half_ = 0; half_ < 2; half_++) {
                int m = m0 + half_ * 8;
                float2 v;
                v.x = acc[mi][ni][half_ * 2 + 0] + b0v;
                v.y = acc[mi][ni][half_ * 2 + 1] + b1v;
                *(float2*)(C + (size_t)m * DD + n) = v;
            }
        }
    }
}

// ===========================================================================
// Mask compaction (unchanged)
// ===========================================================================
__global__ __launch_bounds__(1024) void compact_idx(
    const int* __restrict__ mask, int* __restrict__ rowmap, int* __restrict__ cnt)
{
    const int b = blockIdx.x;
    __shared__ int wsum[32];
    const int t = threadIdx.x;
    const int lane = t & 31;
    const int w = t >> 5;

    const int p0 = 2 * t, p1 = 2 * t + 1;
    const int m0 = mask[b * SS + p0] != 0;
    const int m1 = mask[b * SS + p1] != 0;
    const int local = m0 + m1;

    rowmap[b * SS + p0] = -1;
    rowmap[b * SS + p1] = -1;

    int v = local;
#pragma unroll
    for (int off = 1; off < 32; off <<= 1) {
        int u = __shfl_up_sync(0xffffffffu, v, off);
        if (lane >= off) v += u;
    }
    if (lane == 31) wsum[w] = v;
    __syncthreads();
    if (w == 0) {
        int s = wsum[lane];
#pragma unroll
        for (int off = 1; off < 32; off <<= 1) {
            int u = __shfl_up_sync(0xffffffffu, s, off);
            if (lane >= off) s += u;
        }
        wsum[lane] = s;
    }
    __syncthreads();

    const int base = (w > 0 ? wsum[w - 1] : 0) + (v - local);
    if (m0) rowmap[b * SS + base] = b * SS + p0;
    if (m1) rowmap[b * SS + base + m0] = b * SS + p1;
    if (t == 1023) cnt[b] = wsum[31];
}

// ===========================================================================
// Tensor-core flash attention, single fp16, 2-stage cp.async K/V pipeline.
// smem: Q 16K | 2 KV stages x (K 8K | V 8K).
// ===========================================================================
#define OFF_QH 0
#define OFF_KV 16384
#define ATTN_SMEM (16384 + 2 * 16384)   // 49152

#define ISSUE_KV(ktv, stg)                                                     \
    do {                                                                       \
        _Pragma("unroll") for (int it = 0; it < 4; it++) {                     \
            int i_ = tid + it * 256;                                           \
            int plane_ = i_ >> 9;                                              \
            int idx_ = i_ & 511;                                               \
            int row_ = idx_ >> 3, ch_ = idx_ & 7;                              \
            const __half* sp_ = plane_ ? Vh : Kh;                              \
            const char* src_ = (const char*)(sp_ + (bh + (ktv) + row_) * HD) + ch_ * 16; \
            uint32_t dst_ = sbase + (uint32_t)(OFF_KV + (stg) * 16384 + plane_ * 8192 \
                            + SW128((uint32_t)(row_ * 128 + ch_ * 16)));       \
            asm volatile("cp.async.cg.shared.global [%0], [%1], 16;"           \
                         :: "r"(dst_), "l"(src_) : "memory");                  \
        }                                                                      \
        asm volatile("cp.async.commit_group;" ::: "memory");                   \
    } while (0)

__global__ __launch_bounds__(256, 1) void attn_tc(
    const float* __restrict__ Qf,
    const __half* __restrict__ Kh, const __half* __restrict__ Vh,
    const int* __restrict__ cnt,
    __half* __restrict__ OutH)
{
    extern __shared__ char smb[];
    const uint32_t sbase = smem_u32(smb);

    const int tid = threadIdx.x;
    const int lane = tid & 31;
    const int w = tid >> 5;
    const int b = blockIdx.z, h = blockIdx.y;
    const int q0 = blockIdx.x * 128;
    const int nlive = cnt[b];
    const size_t bh = (size_t)(b * HH + h) * SS;

    const float* Qb = Qf + (bh + q0) * HD;
#pragma unroll
    for (int it = 0; it < 8; it++) {
        int i = tid + it * 256;
        int row = i >> 4, c4 = (i & 15) * 4;
        float4 v = *(const float4*)(Qb + (size_t)row * HD + c4);
        uint32_t sw = SW128((uint32_t)(row * 128 + c4 * 2));
        *(uint2*)(smb + OFF_QH + sw) = make_uint2(pack2h(v.x, v.y), pack2h(v.z, v.w));
    }
    __syncthreads();

    uint32_t qh[4][4];
    {
        const int grp = lane >> 3;
        const int arow = w * 16 + (grp & 1) * 8 + (lane & 7);
        const int adb = (grp >> 1) * 16;
#pragma unroll
        for (int kc = 0; kc < 4; kc++) {
            uint32_t sw = SW128((uint32_t)(arow * 128 + kc * 32 + adb));
            ldmatrix_x4(qh[kc][0], qh[kc][1], qh[kc][2], qh[kc][3], sbase + OFF_QH + sw);
        }
    }

    float Oacc[8][4];
#pragma unroll
    for (int i = 0; i < 8; i++)
#pragma unroll
        for (int j = 0; j < 4; j++) Oacc[i][j] = 0.f;
    float m0r = -1e30f, m1r = -1e30f, l0r = 0.f, l1r = 0.f;

    const int grp = lane >> 3;
    const int k_keyoff = (grp >> 1) * 8 + (lane & 7);
    const int k_dboff = (grp & 1) * 16;
    const int v_keyoff = (grp & 1) * 8 + (lane & 7);
    const int v_hdoff = (grp >> 1) * 16;

    const int ntile = (nlive + 63) >> 6;
    ISSUE_KV(0, 0);

    for (int t = 0; t < ntile; t++) {
        const int kt = t * 64;
        asm volatile("cp.async.wait_group 0;" ::: "memory");
        __syncthreads();
        if (t + 1 < ntile) ISSUE_KV(kt + 64, (t + 1) & 1);
        const uint32_t kvb = (uint32_t)(OFF_KV + (t & 1) * 16384);

        float sc[8][4];
#pragma unroll
        for (int i = 0; i < 8; i++)
#pragma unroll
            for (int j = 0; j < 4; j++) sc[i][j] = 0.f;

#pragma unroll
        for (int kc = 0; kc < 4; kc++) {
#pragma unroll
            for (int np = 0; np < 4; np++) {
                uint32_t swk = kvb + SW128((uint32_t)((np * 16 + k_keyoff) * 128 + kc * 32 + k_dboff));
                uint32_t kh0, kh1, kh2, kh3;
                ldmatrix_x4(kh0, kh1, kh2, kh3, sbase + swk);
                mma_f16(sc[2 * np], qh[kc][0], qh[kc][1], qh[kc][2], qh[kc][3], kh0, kh1);
                mma_f16(sc[2 * np + 1], qh[kc][0], qh[kc][1], qh[kc][2], qh[kc][3], kh2, kh3);
            }
        }

        const bool tail = (kt + 64 > nlive);
        const int colbase = kt + (lane & 3) * 2;
#pragma unroll
        for (int i = 0; i < 8; i++) {
#pragma unroll
            for (int j = 0; j < 4; j++) sc[i][j] *= 0.125f;
        }
        if (tail) {
#pragma unroll
            for (int i = 0; i < 8; i++) {
                int c0 = colbase + i * 8;
                float bia0 = (c0 < nlive) ? 0.f : -1e9f;
                float bia1 = (c0 + 1 < nlive) ? 0.f : -1e9f;
                sc[i][0] += bia0; sc[i][1] += bia1;
                sc[i][2] += bia0; sc[i][3] += bia1;
            }
        }
        {
            float mx = sc[0][0];
#pragma unroll
            for (int i = 0; i < 8; i++) { mx = fmaxf(mx, sc[i][0]); mx = fmaxf(mx, sc[i][1]); }
            mx = fmaxf(mx, __shfl_xor_sync(0xffffffffu, mx, 1));
            mx = fmaxf(mx, __shfl_xor_sync(0xffffffffu, mx, 2));
            float nm = fmaxf(m0r, mx);
            float corr = __expf(m0r - nm);
            float ps = 0.f;
#pragma unroll
            for (int i = 0; i < 8; i++) {
                sc[i][0] = __expf(sc[i][0] - nm); ps += sc[i][0];
                sc[i][1] = __expf(sc[i][1] - nm); ps += sc[i][1];
            }
            ps += __shfl_xor_sync(0xffffffffu, ps, 1);
            ps += __shfl_xor_sync(0xffffffffu, ps, 2);
            l0r = l0r * corr + ps;
            m0r = nm;
#pragma unroll
            for (int i = 0; i < 8; i++) { Oacc[i][0] *= corr; Oacc[i][1] *= corr; }
        }
        {
            float mx = sc[0][2];
#pragma unroll
            for (int i = 0; i < 8; i++) { mx = fmaxf(mx, sc[i][2]); mx = fmaxf(mx, sc[i][3]); }
            mx = fmaxf(mx, __shfl_xor_sync(0xffffffffu, mx, 1));
            mx = fmaxf(mx, __shfl_xor_sync(0xffffffffu, mx, 2));
            float nm = fmaxf(m1r, mx);
            float corr = __expf(m1r - nm);
            float ps = 0.f;
#pragma unroll
            for (int i = 0; i < 8; i++) {
                sc[i][2] = __expf(sc[i][2] - nm); ps += sc[i][2];
                sc[i][3] = __expf(sc[i][3] - nm); ps += sc[i][3];
            }
            ps += __shfl_xor_sync(0xffffffffu, ps, 1);
            ps += __shfl_xor_sync(0xffffffffu, ps, 2);
            l1r = l1r * corr + ps;
            m1r = nm;
#pragma unroll
            for (int i = 0; i < 8; i++) { Oacc[i][2] *= corr; Oacc[i][3] *= corr; }
        }

#pragma unroll
        for (int kc = 0; kc < 4; kc++) {
            uint32_t ah0 = pack2h(sc[2 * kc][0], sc[2 * kc][1]);
            uint32_t ah1 = pack2h(sc[2 * kc][2], sc[2 * kc][3]);
            uint32_t ah2 = pack2h(sc[2 * kc + 1][0], sc[2 * kc + 1][1]);
            uint32_t ah3 = pack2h(sc[2 * kc + 1][2], sc[2 * kc + 1][3]);
#pragma unroll
            for (int np = 0; np < 4; np++) {
                uint32_t swv = kvb + 8192u + SW128((uint32_t)((kc * 16 + v_keyoff) * 128 + np * 32 + v_hdoff));
                uint32_t vh0, vh1, vh2, vh3;
                ldmatrix_x4_trans(vh0, vh1, vh2, vh3, sbase + swv);
                mma_f16(Oacc[2 * np], ah0, ah1, ah2, ah3, vh0, vh1);
                mma_f16(Oacc[2 * np + 1], ah0, ah1, ah2, ah3, vh2, vh3);
            }
        }
    }

    // --- epilogue: write attn-out fp16 ---
    const float inv0 = 1.0f / l0r;
    const float inv1 = 1.0f / l1r;
    const int rg0 = q0 + w * 16 + (lane >> 2);
    const int rg1 = rg0 + 8;
    const int cb = h * HD + (lane & 3) * 2;
#pragma unroll
    for (int nt = 0; nt < 8; nt++) {
        int col = cb + nt * 8;
        size_t ix0 = ((size_t)(b * SS + rg0)) * DD + col;
        *(uint32_t*)(OutH + ix0) = pack2h(Oacc[nt][0] * inv0, Oacc[nt][1] * inv0);
        size_t ix1 = ((size_t)(b * SS + rg1)) * DD + col;
        *(uint32_t*)(OutH + ix1) = pack2h(Oacc[nt][2] * inv1, Oacc[nt][3] * inv1);
    }
}

// ---------------------------------------------------------------------------
extern "C" void kernel_launch(void* const* d_in, const int* in_sizes, int n_in,
                              void* d_out, int out_size)
{
    const float* xq = (const float*)d_in[0];
    const float* xk = (const float*)d_in[1];
    const float* xv = (const float*)d_in[2];
    const int*   mask = (const int*)d_in[3];
    const float* wq = (const float*)d_in[4];
    const float* bq = (const float*)d_in[5];
    const float* wk = (const float*)d_in[6];
    const float* bk = (const float*)d_in[7];
    const float* wv = (const float*)d_in[8];
    const float* bv = (const float*)d_in[9];
    const float* wo = (const float*)d_in[10];
    const float* bo = (const float*)d_in[11];
    float* out = (float*)d_out;

    float* Qp;
    __half *Xhp, *Whp, *Khp, *Vhp, *Ahp;
    int *mapp, *cntp;
    cudaGetSymbolAddress((void**)&Qp, g_Q);
    cudaGetSymbolAddress((void**)&Xhp, g_Xh);
    cudaGetSymbolAddress((void**)&Whp, g_Wh);
    cudaGetSymbolAddress((void**)&Khp, g_Kh);
    cudaGetSymbolAddress((void**)&Vhp, g_Vh);
    cudaGetSymbolAddress((void**)&Ahp, g_Ah);
    cudaGetSymbolAddress((void**)&mapp, g_map);
    cudaGetSymbolAddress((void**)&cntp, g_cnt);

    cudaFuncSetAttribute(attn_tc,
                         cudaFuncAttributeMaxDynamicSharedMemorySize, ATTN_SMEM);
    cudaFuncSetAttribute(tc_gemm_qkv,
                         cudaFuncAttributeMaxDynamicSharedMemorySize, GEMM_SMEM_P);
    cudaFuncSetAttribute(tc_gemm_out,
                         cudaFuncAttributeMaxDynamicSharedMemorySize, GEMM_SMEM_P);

    compact_idx<<<BB, 1024>>>(mask, mapp, cntp);
    cvt_x<<<dim3(MM * DD / 4 / 256, 1, 3), 256>>>(xq, xk, xv, Xhp);
    cvt_w<<<dim3(DD * DD / 4 / 256, 1, 4), 256>>>(wq, wk, wv, wo, Whp);

    tc_gemm_qkv<<<dim3(DD / 256, MM / 128, 3), 256, GEMM_SMEM_P>>>(
        Xhp, Whp, bq, bk, bv, Qp, Khp, Vhp, mapp, cntp);

    attn_tc<<<dim3(SS / 128, HH, BB), 256, ATTN_SMEM>>>(
        Qp, Khp, Vhp, cntp, Ahp);

    tc_gemm_out<<<dim3(DD / 256, MM / 128), 256, GEMM_SMEM_P>>>(
        Ahp, Whp, bo, out);
}